// round 2
// baseline (speedup 1.0000x reference)
#include <cuda_runtime.h>

// Problem constants (FullAttention_73650099192077)
#define B_SZ 4
#define L_Q  2048
#define S_K  2048
#define H_N  8
#define E_N  64
#define D_N  64

#define BM 64           // query rows per CTA
#define BN 64           // key cols per S-tile
#define QSTR 68         // padded row stride (floats) for transposed Q/K tiles
#define NTHREADS 256

// Dynamic smem layout (floats):
//   qT  [64][QSTR]   (E-major, pre-scaled Q^T)
//   kT  [64][QSTR]   (E-major K^T)  -- aliased with p[64][64] between phases
//   vs  [64][64]     (V tile, row-major [c][d])
#define SMEM_FLOATS (2 * 64 * QSTR + 64 * 64)

__global__ __launch_bounds__(NTHREADS)
void fullattn_fp32_kernel(const float* __restrict__ Q,
                          const float* __restrict__ K,
                          const float* __restrict__ V,
                          float* __restrict__ O)
{
    extern __shared__ float smem[];
    float* qT = smem;                    // [64][QSTR]
    float* kT = smem + 64 * QSTR;        // [64][QSTR]; reused as p[64][64]
    float* vs = smem + 2 * 64 * QSTR;    // [64][64]

    const int t  = threadIdx.x;
    const int tx = t & 15;               // 16 threads per row-group (cols)
    const int ty = t >> 4;               // 16 row-groups of 4 rows
    const int l0 = blockIdx.x * BM;
    const int bh = blockIdx.y;
    const int b  = bh >> 3;              // / H_N
    const int h  = bh & 7;               // % H_N

    const float scale = 0.125f;          // 1/sqrt(E)

    // ---- load Q tile, transposed + pre-scaled: qT[e][r] = Q[b, l0+r, h, e] * scale
    {
        const float* qbase = Q + ((b * L_Q + l0) * H_N + h) * E_N;
        #pragma unroll
        for (int kk = 0; kk < 4; kk++) {
            int idx = kk * NTHREADS + t;
            int r = idx >> 4;
            int g = idx & 15;
            float4 qv = *reinterpret_cast<const float4*>(qbase + r * (H_N * E_N) + g * 4);
            qT[(g * 4 + 0) * QSTR + r] = qv.x * scale;
            qT[(g * 4 + 1) * QSTR + r] = qv.y * scale;
            qT[(g * 4 + 2) * QSTR + r] = qv.z * scale;
            qT[(g * 4 + 3) * QSTR + r] = qv.w * scale;
        }
    }

    // Online-softmax state: 4 rows per thread group; m,l replicated over the 16 tx lanes
    float m[4], l[4], o[4][4];
    #pragma unroll
    for (int i = 0; i < 4; i++) {
        m[i] = -1e30f;
        l[i] = 0.0f;
        #pragma unroll
        for (int j = 0; j < 4; j++) o[i][j] = 0.0f;
    }

    const float* kbase = K + ((b * S_K) * H_N + h) * E_N;
    const float* vbase = V + ((b * S_K) * H_N + h) * D_N;

    for (int s0 = 0; s0 < S_K; s0 += BN) {
        // ---- load K^T (kT[e][c]) and V (vs[c][d]) tiles
        #pragma unroll
        for (int kk = 0; kk < 4; kk++) {
            int idx = kk * NTHREADS + t;
            int c = idx >> 4;
            int g = idx & 15;
            float4 kv = *reinterpret_cast<const float4*>(kbase + (s0 + c) * (H_N * E_N) + g * 4);
            kT[(g * 4 + 0) * QSTR + c] = kv.x;
            kT[(g * 4 + 1) * QSTR + c] = kv.y;
            kT[(g * 4 + 2) * QSTR + c] = kv.z;
            kT[(g * 4 + 3) * QSTR + c] = kv.w;
            float4 vv = *reinterpret_cast<const float4*>(vbase + (s0 + c) * (H_N * D_N) + g * 4);
            *reinterpret_cast<float4*>(&vs[c * 64 + g * 4]) = vv;
        }
        __syncthreads();

        // ---- scores: s[i][j] = sum_e qT[e][ty*4+i] * kT[e][tx*4+j]  (scale folded into qT)
        float sacc[4][4];
        #pragma unroll
        for (int i = 0; i < 4; i++)
            #pragma unroll
            for (int j = 0; j < 4; j++) sacc[i][j] = 0.0f;

        #pragma unroll 16
        for (int e = 0; e < 64; e++) {
            float4 qv = *reinterpret_cast<const float4*>(&qT[e * QSTR + ty * 4]);
            float4 kv = *reinterpret_cast<const float4*>(&kT[e * QSTR + tx * 4]);
            float qa[4] = {qv.x, qv.y, qv.z, qv.w};
            float ka[4] = {kv.x, kv.y, kv.z, kv.w};
            #pragma unroll
            for (int i = 0; i < 4; i++)
                #pragma unroll
                for (int j = 0; j < 4; j++)
                    sacc[i][j] = fmaf(qa[i], ka[j], sacc[i][j]);
        }
        __syncthreads();   // everyone done reading kT -> safe to overwrite with p

        // ---- online softmax (row reductions across the 16 tx lanes via shfl)
        float p[4][4];
        #pragma unroll
        for (int i = 0; i < 4; i++) {
            float tm = sacc[i][0];
            #pragma unroll
            for (int j = 1; j < 4; j++) tm = fmaxf(tm, sacc[i][j]);
            #pragma unroll
            for (int off = 1; off < 16; off <<= 1)
                tm = fmaxf(tm, __shfl_xor_sync(0xffffffffu, tm, off));

            float nm = fmaxf(m[i], tm);
            float alpha = __expf(m[i] - nm);
            m[i] = nm;

            float rs = 0.0f;
            #pragma unroll
            for (int j = 0; j < 4; j++) {
                p[i][j] = __expf(sacc[i][j] - nm);
                rs += p[i][j];
            }
            #pragma unroll
            for (int off = 1; off < 16; off <<= 1)
                rs += __shfl_xor_sync(0xffffffffu, rs, off);

            l[i] = l[i] * alpha + rs;
            #pragma unroll
            for (int j = 0; j < 4; j++) o[i][j] *= alpha;
        }

        // ---- write p into the kT buffer (stride 64), float4 per row
        float* ps = kT;
        #pragma unroll
        for (int i = 0; i < 4; i++) {
            float4 pv = make_float4(p[i][0], p[i][1], p[i][2], p[i][3]);
            *reinterpret_cast<float4*>(&ps[(ty * 4 + i) * 64 + tx * 4]) = pv;
        }
        __syncthreads();   // p visible to all

        // ---- PV: o[i][j] += sum_c p[ty*4+i][c] * vs[c][tx*4+j]
        #pragma unroll 8
        for (int c = 0; c < 64; c++) {
            float4 vv = *reinterpret_cast<const float4*>(&vs[c * 64 + tx * 4]);
            float va[4] = {vv.x, vv.y, vv.z, vv.w};
            float pa[4];
            #pragma unroll
            for (int i = 0; i < 4; i++) pa[i] = ps[(ty * 4 + i) * 64 + c];  // broadcast
            #pragma unroll
            for (int i = 0; i < 4; i++)
                #pragma unroll
                for (int j = 0; j < 4; j++)
                    o[i][j] = fmaf(pa[i], va[j], o[i][j]);
        }
        __syncthreads();   // done with ps/vs -> next tile load may overwrite
    }

    // ---- epilogue: normalize and store O[b, l0+r, h, d]
    float* obase = O + ((b * L_Q + l0) * H_N + h) * D_N;
    #pragma unroll
    for (int i = 0; i < 4; i++) {
        float inv = 1.0f / l[i];
        float4 ov = make_float4(o[i][0] * inv, o[i][1] * inv, o[i][2] * inv, o[i][3] * inv);
        *reinterpret_cast<float4*>(obase + (ty * 4 + i) * (H_N * D_N) + tx * 4) = ov;
    }
}

extern "C" void kernel_launch(void* const* d_in, const int* in_sizes, int n_in,
                              void* d_out, int out_size)
{
    const float* Q = (const float*)d_in[0];
    const float* K = (const float*)d_in[1];
    const float* V = (const float*)d_in[2];
    float* O = (float*)d_out;

    (void)in_sizes; (void)n_in; (void)out_size;

    // 51200 B dynamic smem > 48KB default -> raise the cap (idempotent, capture-safe)
    cudaFuncSetAttribute(fullattn_fp32_kernel,
                         cudaFuncAttributeMaxDynamicSharedMemorySize,
                         SMEM_FLOATS * (int)sizeof(float));

    dim3 grid(L_Q / BM, B_SZ * H_N);   // 32 x 32 CTAs
    fullattn_fp32_kernel<<<grid, NTHREADS, SMEM_FLOATS * sizeof(float)>>>(Q, K, V, O);
}